// round 3
// baseline (speedup 1.0000x reference)
#include <cuda_runtime.h>
#include <math.h>

#define Nn 4096
#define Hh 500
#define Dd 8
#define NHEADS 5

// ---------------- scratch (static device globals; no allocation) ----------------
__device__ float g_xA[Nn * Hh];
__device__ float g_xB[Nn * Hh];
__device__ float g_h[Nn * Hh];
__device__ float g_c[Nn * Hh];
__device__ float g_gates[Nn * 4 * Hh];
__device__ float g_z[Nn * NHEADS * Hh];
__device__ float g_el[Nn * NHEADS];
__device__ float g_er[Nn * NHEADS];

// ---------------- utility kernels ----------------
__global__ void zero_k(float* p, int n) {
    int i = blockIdx.x * blockDim.x + threadIdx.x;
    if (i < n) p[i] = 0.f;
}

__global__ void embed_k(const int* __restrict__ ids, const float* __restrict__ emb,
                        float* __restrict__ x) {
    int i = blockIdx.x * blockDim.x + threadIdx.x;
    if (i < Nn * Hh) {
        int n = i / Hh, c = i % Hh;
        x[i] = emb[ids[n] * Hh + c];
    }
}

// ---------------- generic fp32 tiled GEMM with fused concat-K + gather ----------------
// C[M, Ncols] = act( A @ B + bias0 + bias1 )
// A (virtual, K = 500 or 1000):
//   part0 rows: X0[ gather? nbr[m*Dd+t] : m ][k]     k in [0,500)
//   part1 rows: X1[ m ][k-500]                        (skipped if X1 == nullptr)
// B0/B1 are [500, Ncols] row-major, ld == Ncols.
__global__ __launch_bounds__(256) void gemm_concat(
    const float* __restrict__ X0, const int* __restrict__ nbr, int t,
    const float* __restrict__ X1,
    const float* __restrict__ B0, const float* __restrict__ B1,
    const float* __restrict__ bias0, const float* __restrict__ bias1,
    float* __restrict__ C, int Ncols, int act)
{
    __shared__ float As[4][128];
    __shared__ float Bs[4][128];
    __shared__ int rix[128];

    const int tid = threadIdx.x;
    const int bm = blockIdx.y * 128;
    const int bn = blockIdx.x * 128;
    const int tx = tid & 15, ty = tid >> 4;

    if (tid < 128) {
        int m = bm + tid;
        rix[tid] = nbr ? nbr[m * Dd + t] : m;
    }

    float acc[8][8];
#pragma unroll
    for (int i = 0; i < 8; i++)
#pragma unroll
        for (int j = 0; j < 8; j++) acc[i][j] = 0.f;

    __syncthreads();

    for (int part = 0; part < 2; ++part) {
        const float* X = part ? X1 : X0;
        const float* B = part ? B1 : B0;
        if (X == nullptr) break;

        for (int k0 = 0; k0 < Hh; k0 += 4) {
            float4 av = make_float4(0.f, 0.f, 0.f, 0.f);
            float4 bv = make_float4(0.f, 0.f, 0.f, 0.f);
            int n4 = 0, kk = 0;
            if (tid < 128) {
                int r = (part == 0) ? rix[tid] : (bm + tid);
                av = *reinterpret_cast<const float4*>(&X[r * Hh + k0]);
            } else {
                int j = tid - 128;
                kk = j >> 5;          // 0..3
                n4 = (j & 31) << 2;   // 0,4,...,124
                int col = bn + n4;
                if (col < Ncols)
                    bv = *reinterpret_cast<const float4*>(&B[(k0 + kk) * Ncols + col]);
            }
            __syncthreads();   // previous tile fully consumed
            if (tid < 128) {
                As[0][tid] = av.x; As[1][tid] = av.y; As[2][tid] = av.z; As[3][tid] = av.w;
            } else {
                *reinterpret_cast<float4*>(&Bs[kk][n4]) = bv;
            }
            __syncthreads();

#pragma unroll
            for (int k = 0; k < 4; k++) {
                // vectorized shared loads: 2x LDS.128 per operand
                float4 a0 = *reinterpret_cast<const float4*>(&As[k][ty * 8]);
                float4 a1 = *reinterpret_cast<const float4*>(&As[k][ty * 8 + 4]);
                float4 b0 = *reinterpret_cast<const float4*>(&Bs[k][tx * 8]);
                float4 b1 = *reinterpret_cast<const float4*>(&Bs[k][tx * 8 + 4]);
                float a[8] = {a0.x, a0.y, a0.z, a0.w, a1.x, a1.y, a1.z, a1.w};
                float b[8] = {b0.x, b0.y, b0.z, b0.w, b1.x, b1.y, b1.z, b1.w};
#pragma unroll
                for (int i = 0; i < 8; i++)
#pragma unroll
                    for (int j = 0; j < 8; j++) acc[i][j] = fmaf(a[i], b[j], acc[i][j]);
            }
        }
    }

#pragma unroll
    for (int i = 0; i < 8; i++) {
        int m = bm + ty * 8 + i;
#pragma unroll
        for (int j = 0; j < 8; j++) {
            int n = bn + tx * 8 + j;
            if (n < Ncols) {
                float v = acc[i][j];
                if (bias0) v += bias0[n];
                if (bias1) v += bias1[n];
                if (act) v = fmaxf(v, 0.f);
                C[(size_t)m * Ncols + n] = v;
            }
        }
    }
}

// ---------------- LSTM cell update (torch gate order i,f,g,o) ----------------
// first=1: previous c is implicitly zero (t==0), so skip reading g_c.
__global__ void lstm_cell_k(int first) {
    int i = blockIdx.x * blockDim.x + threadIdx.x;
    if (i >= Nn * Hh) return;
    int n = i / Hh, j = i % Hh;
    const float* g = g_gates + (size_t)n * (4 * Hh);
    float gi = g[j];
    float gf = g[j + Hh];
    float gg = g[j + 2 * Hh];
    float go = g[j + 3 * Hh];
    float si = 1.f / (1.f + expf(-gi));
    float sf = 1.f / (1.f + expf(-gf));
    float so = 1.f / (1.f + expf(-go));
    float cprev = first ? 0.f : g_c[i];
    float c = sf * cprev + si * tanhf(gg);
    g_c[i] = c;
    g_h[i] = so * tanhf(c);
}

// ---------------- GAT attention scores: el/er per (node, head) ----------------
__global__ void gat_scores_k(const float* __restrict__ al, const float* __restrict__ ar) {
    int w = (blockIdx.x * blockDim.x + threadIdx.x) >> 5;
    int lane = threadIdx.x & 31;
    if (w >= Nn * NHEADS) return;
    int n = w / NHEADS, hd = w % NHEADS;
    const float* zr = g_z + (size_t)n * (NHEADS * Hh) + hd * Hh;
    float sl = 0.f, sr = 0.f;
    for (int c = lane; c < Hh; c += 32) {
        float zv = zr[c];
        sl = fmaf(zv, al[hd * Hh + c], sl);
        sr = fmaf(zv, ar[hd * Hh + c], sr);
    }
#pragma unroll
    for (int o = 16; o; o >>= 1) {
        sl += __shfl_xor_sync(0xFFFFFFFFu, sl, o);
        sr += __shfl_xor_sync(0xFFFFFFFFu, sr, o);
    }
    if (lane == 0) { g_el[w] = sl; g_er[w] = sr; }
}

// ---------------- fused GAT aggregate + relu + head-mean + elu + readout + segsum ----------------
__global__ __launch_bounds__(256) void gat_final_k(
    const int* __restrict__ nbr, const int* __restrict__ gid,
    const float* __restrict__ Wr, const float* __restrict__ br,
    float* __restrict__ out)
{
    int n = blockIdx.x;
    int tid = threadIdx.x;
    __shared__ float alpha[NHEADS][Dd];
    __shared__ int nb[Dd];
    __shared__ float red[256];

    if (tid < Dd) nb[tid] = nbr[n * Dd + tid];
    __syncthreads();

    if (tid < NHEADS * Dd) {
        int hd = tid / Dd, d = tid % Dd;
        float e = g_el[nb[d] * NHEADS + hd] + g_er[n * NHEADS + hd];
        alpha[hd][d] = (e > 0.f) ? e : 0.2f * e;   // leaky_relu slope 0.2
    }
    __syncthreads();
    if (tid < NHEADS) {
        float mx = -1e30f;
#pragma unroll
        for (int d = 0; d < Dd; d++) mx = fmaxf(mx, alpha[tid][d]);
        float ex[Dd]; float s = 0.f;
#pragma unroll
        for (int d = 0; d < Dd; d++) { ex[d] = expf(alpha[tid][d] - mx); s += ex[d]; }
        float inv = 1.f / s;
#pragma unroll
        for (int d = 0; d < Dd; d++) alpha[tid][d] = ex[d] * inv;
    }
    __syncthreads();

    float accum = 0.f;
    for (int c = tid; c < Hh; c += 256) {
        float mean = 0.f;
#pragma unroll
        for (int hd = 0; hd < NHEADS; hd++) {
            float s = 0.f;
#pragma unroll
            for (int d = 0; d < Dd; d++)
                s = fmaf(alpha[hd][d],
                         g_z[(size_t)nb[d] * (NHEADS * Hh) + hd * Hh + c], s);
            mean += fmaxf(s, 0.f);    // relu applied per (n,head,c) BEFORE mean
        }
        mean *= (1.f / NHEADS);
        float e = (mean > 0.f) ? mean : (expf(mean) - 1.f);   // elu
        accum = fmaf(e, Wr[c], accum);
    }
    red[tid] = accum;
    __syncthreads();
    for (int s = 128; s > 0; s >>= 1) {
        if (tid < s) red[tid] += red[tid + s];
        __syncthreads();
    }
    if (tid == 0) atomicAdd(&out[gid[n]], red[0] + br[0]);
}

// ---------------- launch ----------------
extern "C" void kernel_launch(void* const* d_in, const int* in_sizes, int n_in,
                              void* d_out, int out_size) {
    const int* node_ids  = (const int*)d_in[0];
    const int* neighbors = (const int*)d_in[1];
    const int* graph_ids = (const int*)d_in[2];
    // d_in[3] = num_graphs (unused; out_size gives G)
    const float* emb = (const float*)d_in[4];
    const float* W[3][7];   // Wih, Whh, bih, bhh, Wself, Wneigh, b
    int p = 5;
    for (int l = 0; l < 3; l++)
        for (int q = 0; q < 7; q++) W[l][q] = (const float*)d_in[p++];
    const float* Wg = (const float*)d_in[p++];
    const float* al = (const float*)d_in[p++];
    const float* ar = (const float*)d_in[p++];
    const float* Wr = (const float*)d_in[p++];
    const float* br = (const float*)d_in[p++];
    float* out = (float*)d_out;

    float *xA, *xB, *h, *gates, *z;
    cudaGetSymbolAddress((void**)&xA, g_xA);
    cudaGetSymbolAddress((void**)&xB, g_xB);
    cudaGetSymbolAddress((void**)&h, g_h);
    cudaGetSymbolAddress((void**)&gates, g_gates);
    cudaGetSymbolAddress((void**)&z, g_z);

    const int NH = Nn * Hh;
    zero_k<<<1, 64>>>(out, out_size);
    embed_k<<<(NH + 255) / 256, 256>>>(node_ids, emb, xA);

    dim3 gGates((4 * Hh + 127) / 128, Nn / 128);      // 16 x 32
    dim3 gFc((Hh + 127) / 128, Nn / 128);             // 4 x 32
    dim3 gZ((NHEADS * Hh + 127) / 128, Nn / 128);     // 20 x 32

    float* xin = xA;
    float* xout = xB;
    for (int l = 0; l < 3; l++) {
        for (int t = 0; t < Dd; t++) {
            // t == 0: h == 0, so the h@Whh half contributes nothing -> skip it.
            gemm_concat<<<gGates, 256>>>(xin, neighbors, t,
                                         (t == 0) ? nullptr : h,
                                         W[l][0], W[l][1], W[l][2], W[l][3],
                                         gates, 4 * Hh, 0);
            lstm_cell_k<<<(NH + 255) / 256, 256>>>(t == 0 ? 1 : 0);
        }
        gemm_concat<<<gFc, 256>>>(xin, nullptr, 0, h,
                                  W[l][4], W[l][5], W[l][6], nullptr,
                                  xout, Hh, 1);
        float* tmp = xin; xin = xout; xout = tmp;
    }

    gemm_concat<<<gZ, 256>>>(xin, nullptr, 0, nullptr,
                             Wg, nullptr, nullptr, nullptr,
                             z, NHEADS * Hh, 0);
    gat_scores_k<<<(Nn * NHEADS * 32 + 127) / 128, 128>>>(al, ar);
    gat_final_k<<<Nn, 256>>>(neighbors, graph_ids, Wr, br, out);
}

// round 5
// speedup vs baseline: 2.2141x; 2.2141x over previous
#include <cuda_runtime.h>
#include <stdint.h>
#include <math.h>

#define Nn 4096
#define Hh 500
#define Dd 8
#define NHEADS 5

#define BM 128
#define BN 128
#define BK 16
#define ASTRIDE 20    // 16 + 4 pad: conflict-free A fragment loads
#define BSTRIDE 132   // 128 + 4 pad: conflict-free B fragment loads

// ---------------- scratch (static device globals; no allocation) ----------------
__device__ float g_xA[Nn * Hh];
__device__ float g_xB[Nn * Hh];
__device__ float g_h[Nn * Hh];
__device__ float g_c[Nn * Hh];
__device__ float g_gates[Nn * 4 * Hh];
__device__ float g_z[Nn * NHEADS * Hh];
__device__ float g_el[Nn * NHEADS];
__device__ float g_er[Nn * NHEADS];

// ---------------- utility kernels ----------------
__global__ void zero_k(float* p, int n) {
    int i = blockIdx.x * blockDim.x + threadIdx.x;
    if (i < n) p[i] = 0.f;
}

__global__ void embed_k(const int* __restrict__ ids, const float* __restrict__ emb,
                        float* __restrict__ x) {
    int i = blockIdx.x * blockDim.x + threadIdx.x;
    if (i < Nn * Hh) {
        int n = i / Hh, c = i % Hh;
        x[i] = emb[ids[n] * Hh + c];
    }
}

// round-to-nearest tf32 (unbiased; keeps accumulated GEMM error ~1e-4)
__device__ __forceinline__ float tf32r(float x) {
    unsigned int u;
    asm("cvt.rna.tf32.f32 %0, %1;" : "=r"(u) : "f"(x));
    return __uint_as_float(u);
}

__device__ __forceinline__ void mma_tf32(float c[4], float a0, float a1, float a2, float a3,
                                         float b0, float b1) {
    asm volatile(
        "mma.sync.aligned.m16n8k8.row.col.f32.tf32.tf32.f32 "
        "{%0,%1,%2,%3}, {%4,%5,%6,%7}, {%8,%9}, {%0,%1,%2,%3};"
        : "+f"(c[0]), "+f"(c[1]), "+f"(c[2]), "+f"(c[3])
        : "r"(__float_as_uint(a0)), "r"(__float_as_uint(a1)),
          "r"(__float_as_uint(a2)), "r"(__float_as_uint(a3)),
          "r"(__float_as_uint(b0)), "r"(__float_as_uint(b1)));
}

// ---------------- tensor-core tf32 GEMM with fused concat-K + gather ----------------
// C[M, Ncols] = act( A @ B + bias0 + bias1 )
// A (virtual, K = 500 or 1000):
//   part0 rows: X0[ nbr? nbr[m*Dd+t] : m ][k]   k in [0,500)
//   part1 rows: X1[ m ][k-500]                   (skipped if X1 == nullptr)
__global__ __launch_bounds__(256, 1) void gemm_mma(
    const float* __restrict__ X0, const int* __restrict__ nbr, int t,
    const float* __restrict__ X1,
    const float* __restrict__ B0, const float* __restrict__ B1,
    const float* __restrict__ bias0, const float* __restrict__ bias1,
    float* __restrict__ C, int Ncols, int act)
{
    __shared__ float As[BM * ASTRIDE];
    __shared__ float Bs[BK * BSTRIDE];
    __shared__ int rix[BM];

    const int tid = threadIdx.x;
    const int bm = blockIdx.y * BM;
    const int bn = blockIdx.x * BN;
    const int lane = tid & 31;
    const int warp = tid >> 5;
    const int g = lane >> 2, tig = lane & 3;
    const int am0 = (warp >> 2) * 64;      // warp M origin (0 or 64)
    const int bn0 = (warp & 3) * 32;       // warp N origin (0,32,64,96)

    // loader roles
    const int ar = tid >> 1;               // A row 0..127
    const int ac = (tid & 1) * 8;          // A col 0 or 8
    const int brw = tid >> 4;              // B row 0..15
    const int bc = (tid & 15) * 8;         // B col 0..120

    if (tid < BM) rix[tid] = nbr ? nbr[(bm + tid) * Dd + t] : (bm + tid);

    float acc[4][4][4];
#pragma unroll
    for (int mt = 0; mt < 4; mt++)
#pragma unroll
        for (int nt = 0; nt < 4; nt++)
#pragma unroll
            for (int r = 0; r < 4; r++) acc[mt][nt][r] = 0.f;

    __syncthreads();

    const int NK = (Hh + BK - 1) / BK;     // 32

    for (int part = 0; part < 2; ++part) {
        const float* X = part ? X1 : X0;
        const float* Bw = part ? B1 : B0;
        if (X == nullptr) break;

        const int arow = (part == 0) ? rix[ar] : (bm + ar);
        const float* Arow = X + (size_t)arow * Hh;

        float a_reg[8], b_reg[8];

        // ---- preload k-tile 0 into registers ----
        {
            const int k0 = 0;
            float4 v0 = *reinterpret_cast<const float4*>(Arow + k0 + ac);
            float4 v1 = *reinterpret_cast<const float4*>(Arow + k0 + ac + 4);
            a_reg[0]=v0.x; a_reg[1]=v0.y; a_reg[2]=v0.z; a_reg[3]=v0.w;
            a_reg[4]=v1.x; a_reg[5]=v1.y; a_reg[6]=v1.z; a_reg[7]=v1.w;
            const int cb = bn + bc;
            const float* Bp = Bw + (size_t)(k0 + brw) * Ncols;
#pragma unroll
            for (int i = 0; i < 8; i++) b_reg[i] = 0.f;
            if (cb < Ncols) {
                float4 w0 = *reinterpret_cast<const float4*>(Bp + cb);
                b_reg[0]=w0.x; b_reg[1]=w0.y; b_reg[2]=w0.z; b_reg[3]=w0.w;
                if (cb + 4 < Ncols) {
                    float4 w1 = *reinterpret_cast<const float4*>(Bp + cb + 4);
                    b_reg[4]=w1.x; b_reg[5]=w1.y; b_reg[6]=w1.z; b_reg[7]=w1.w;
                }
            }
        }

        for (int kt = 0; kt < NK; kt++) {
            // ---- stage registers -> smem (with tf32 rounding) ----
            {
                float* ap = &As[ar * ASTRIDE + ac];
#pragma unroll
                for (int i = 0; i < 8; i++) ap[i] = tf32r(a_reg[i]);
                float* bp = &Bs[brw * BSTRIDE + bc];
#pragma unroll
                for (int i = 0; i < 8; i++) bp[i] = tf32r(b_reg[i]);
            }
            __syncthreads();

            // ---- prefetch next k-tile into registers (overlaps MMA below) ----
            if (kt + 1 < NK) {
                const int k0 = (kt + 1) * BK;
                if (k0 + ac + 8 <= Hh) {
                    float4 v0 = *reinterpret_cast<const float4*>(Arow + k0 + ac);
                    float4 v1 = *reinterpret_cast<const float4*>(Arow + k0 + ac + 4);
                    a_reg[0]=v0.x; a_reg[1]=v0.y; a_reg[2]=v0.z; a_reg[3]=v0.w;
                    a_reg[4]=v1.x; a_reg[5]=v1.y; a_reg[6]=v1.z; a_reg[7]=v1.w;
                } else {
#pragma unroll
                    for (int i = 0; i < 8; i++) {
                        int cc = k0 + ac + i;
                        a_reg[i] = (cc < Hh) ? Arow[cc] : 0.f;
                    }
                }
                const int brow = k0 + brw;
                const int cb = bn + bc;
#pragma unroll
                for (int i = 0; i < 8; i++) b_reg[i] = 0.f;
                if (brow < Hh && cb < Ncols) {
                    const float* Bp = Bw + (size_t)brow * Ncols;
                    float4 w0 = *reinterpret_cast<const float4*>(Bp + cb);
                    b_reg[0]=w0.x; b_reg[1]=w0.y; b_reg[2]=w0.z; b_reg[3]=w0.w;
                    if (cb + 4 < Ncols) {
                        float4 w1 = *reinterpret_cast<const float4*>(Bp + cb + 4);
                        b_reg[4]=w1.x; b_reg[5]=w1.y; b_reg[6]=w1.z; b_reg[7]=w1.w;
                    }
                }
            }

            // ---- tensor-core compute over the staged tile ----
#pragma unroll
            for (int kk = 0; kk < 2; kk++) {
                const int k8 = kk * 8;
                float fa0[4], fa1[4], fa2[4], fa3[4];
#pragma unroll
                for (int mt = 0; mt < 4; mt++) {
                    const int r = am0 + mt * 16 + g;
                    fa0[mt] = As[r * ASTRIDE + k8 + tig];
                    fa1[mt] = As[(r + 8) * ASTRIDE + k8 + tig];
                    fa2[mt] = As[r * ASTRIDE + k8 + tig + 4];
                    fa3[mt] = As[(r + 8) * ASTRIDE + k8 + tig + 4];
                }
                float fb0[4], fb1[4];
#pragma unroll
                for (int nt = 0; nt < 4; nt++) {
                    const int cn = bn0 + nt * 8 + g;
                    fb0[nt] = Bs[(k8 + tig) * BSTRIDE + cn];
                    fb1[nt] = Bs[(k8 + tig + 4) * BSTRIDE + cn];
                }
#pragma unroll
                for (int mt = 0; mt < 4; mt++)
#pragma unroll
                    for (int nt = 0; nt < 4; nt++)
                        mma_tf32(acc[mt][nt], fa0[mt], fa1[mt], fa2[mt], fa3[mt],
                                 fb0[nt], fb1[nt]);
            }
            __syncthreads();
        }
    }

    // ---- epilogue: bias + optional relu, float2 stores ----
#pragma unroll
    for (int mt = 0; mt < 4; mt++) {
        const int row0 = bm + am0 + mt * 16 + g;
#pragma unroll
        for (int nt = 0; nt < 4; nt++) {
            const int col = bn + bn0 + nt * 8 + 2 * tig;
            if (col < Ncols) {
                float bia = 0.f;
                float bib = 0.f;
                if (bias0) { bia = bias0[col]; bib = bias0[col + 1]; }
                if (bias1) { bia += bias1[col]; bib += bias1[col + 1]; }
                float v0 = acc[mt][nt][0] + bia;
                float v1 = acc[mt][nt][1] + bib;
                float v2 = acc[mt][nt][2] + bia;
                float v3 = acc[mt][nt][3] + bib;
                if (act) {
                    v0 = fmaxf(v0, 0.f); v1 = fmaxf(v1, 0.f);
                    v2 = fmaxf(v2, 0.f); v3 = fmaxf(v3, 0.f);
                }
                *reinterpret_cast<float2*>(&C[(size_t)row0 * Ncols + col]) =
                    make_float2(v0, v1);
                *reinterpret_cast<float2*>(&C[(size_t)(row0 + 8) * Ncols + col]) =
                    make_float2(v2, v3);
            }
        }
    }
}

// ---------------- LSTM cell update (torch gate order i,f,g,o) ----------------
__global__ void lstm_cell_k(int first) {
    int i = blockIdx.x * blockDim.x + threadIdx.x;
    if (i >= Nn * Hh) return;
    int n = i / Hh, j = i % Hh;
    const float* g = g_gates + (size_t)n * (4 * Hh);
    float gi = g[j];
    float gf = g[j + Hh];
    float gg = g[j + 2 * Hh];
    float go = g[j + 3 * Hh];
    float si = 1.f / (1.f + expf(-gi));
    float sf = 1.f / (1.f + expf(-gf));
    float so = 1.f / (1.f + expf(-go));
    float cprev = first ? 0.f : g_c[i];
    float c = sf * cprev + si * tanhf(gg);
    g_c[i] = c;
    g_h[i] = so * tanhf(c);
}

// ---------------- GAT attention scores: el/er per (node, head) ----------------
__global__ void gat_scores_k(const float* __restrict__ al, const float* __restrict__ ar) {
    int w = (blockIdx.x * blockDim.x + threadIdx.x) >> 5;
    int lane = threadIdx.x & 31;
    if (w >= Nn * NHEADS) return;
    int n = w / NHEADS, hd = w % NHEADS;
    const float* zr = g_z + (size_t)n * (NHEADS * Hh) + hd * Hh;
    float sl = 0.f, sr = 0.f;
    for (int c = lane; c < Hh; c += 32) {
        float zv = zr[c];
        sl = fmaf(zv, al[hd * Hh + c], sl);
        sr = fmaf(zv, ar[hd * Hh + c], sr);
    }
#pragma unroll
    for (int o = 16; o; o >>= 1) {
        sl += __shfl_xor_sync(0xFFFFFFFFu, sl, o);
        sr += __shfl_xor_sync(0xFFFFFFFFu, sr, o);
    }
    if (lane == 0) { g_el[w] = sl; g_er[w] = sr; }
}

// ---------------- fused GAT aggregate + relu + head-mean + elu + readout + segsum ----------------
__global__ __launch_bounds__(256) void gat_final_k(
    const int* __restrict__ nbr, const int* __restrict__ gid,
    const float* __restrict__ Wr, const float* __restrict__ br,
    float* __restrict__ out)
{
    int n = blockIdx.x;
    int tid = threadIdx.x;
    __shared__ float alpha[NHEADS][Dd];
    __shared__ int nb[Dd];
    __shared__ float red[256];

    if (tid < Dd) nb[tid] = nbr[n * Dd + tid];
    __syncthreads();

    if (tid < NHEADS * Dd) {
        int hd = tid / Dd, d = tid % Dd;
        float e = g_el[nb[d] * NHEADS + hd] + g_er[n * NHEADS + hd];
        alpha[hd][d] = (e > 0.f) ? e : 0.2f * e;   // leaky_relu slope 0.2
    }
    __syncthreads();
    if (tid < NHEADS) {
        float mx = -1e30f;
#pragma unroll
        for (int d = 0; d < Dd; d++) mx = fmaxf(mx, alpha[tid][d]);
        float ex[Dd]; float s = 0.f;
#pragma unroll
        for (int d = 0; d < Dd; d++) { ex[d] = expf(alpha[tid][d] - mx); s += ex[d]; }
        float inv = 1.f / s;
#pragma unroll
        for (int d = 0; d < Dd; d++) alpha[tid][d] = ex[d] * inv;
    }
    __syncthreads();

    float accum = 0.f;
    for (int c = tid; c < Hh; c += 256) {
        float mean = 0.f;
#pragma unroll
        for (int hd = 0; hd < NHEADS; hd++) {
            float s = 0.f;
#pragma unroll
            for (int d = 0; d < Dd; d++)
                s = fmaf(alpha[hd][d],
                         g_z[(size_t)nb[d] * (NHEADS * Hh) + hd * Hh + c], s);
            mean += fmaxf(s, 0.f);    // relu BEFORE head-mean
        }
        mean *= (1.f / NHEADS);
        float e = (mean > 0.f) ? mean : (expf(mean) - 1.f);   // elu
        accum = fmaf(e, Wr[c], accum);
    }
    red[tid] = accum;
    __syncthreads();
    for (int s = 128; s > 0; s >>= 1) {
        if (tid < s) red[tid] += red[tid + s];
        __syncthreads();
    }
    if (tid == 0) atomicAdd(&out[gid[n]], red[0] + br[0]);
}

// ---------------- launch ----------------
extern "C" void kernel_launch(void* const* d_in, const int* in_sizes, int n_in,
                              void* d_out, int out_size) {
    const int* node_ids  = (const int*)d_in[0];
    const int* neighbors = (const int*)d_in[1];
    const int* graph_ids = (const int*)d_in[2];
    // d_in[3] = num_graphs (unused; out_size gives G)
    const float* emb = (const float*)d_in[4];
    const float* W[3][7];   // Wih, Whh, bih, bhh, Wself, Wneigh, b
    int p = 5;
    for (int l = 0; l < 3; l++)
        for (int q = 0; q < 7; q++) W[l][q] = (const float*)d_in[p++];
    const float* Wg = (const float*)d_in[p++];
    const float* al = (const float*)d_in[p++];
    const float* ar = (const float*)d_in[p++];
    const float* Wr = (const float*)d_in[p++];
    const float* br = (const float*)d_in[p++];
    float* out = (float*)d_out;

    float *xA, *xB, *h, *gates, *z;
    cudaGetSymbolAddress((void**)&xA, g_xA);
    cudaGetSymbolAddress((void**)&xB, g_xB);
    cudaGetSymbolAddress((void**)&h, g_h);
    cudaGetSymbolAddress((void**)&gates, g_gates);
    cudaGetSymbolAddress((void**)&z, g_z);

    const int NH = Nn * Hh;
    zero_k<<<1, 64>>>(out, out_size);
    embed_k<<<(NH + 255) / 256, 256>>>(node_ids, emb, xA);

    dim3 gGates((4 * Hh + BN - 1) / BN, Nn / BM);      // 16 x 32
    dim3 gFc((Hh + BN - 1) / BN, Nn / BM);             // 4 x 32
    dim3 gZ((NHEADS * Hh + BN - 1) / BN, Nn / BM);     // 20 x 32

    float* xin = xA;
    float* xout = xB;
    for (int l = 0; l < 3; l++) {
        for (int t = 0; t < Dd; t++) {
            // t == 0: h == 0 -> skip the h@Whh half entirely.
            gemm_mma<<<gGates, 256>>>(xin, neighbors, t,
                                      (t == 0) ? nullptr : h,
                                      W[l][0], W[l][1], W[l][2], W[l][3],
                                      gates, 4 * Hh, 0);
            lstm_cell_k<<<(NH + 255) / 256, 256>>>(t == 0 ? 1 : 0);
        }
        gemm_mma<<<gFc, 256>>>(xin, nullptr, 0, h,
                               W[l][4], W[l][5], W[l][6], nullptr,
                               xout, Hh, 1);
        float* tmp = xin; xin = xout; xout = tmp;
    }

    gemm_mma<<<gZ, 256>>>(xin, nullptr, 0, nullptr,
                          Wg, nullptr, nullptr, nullptr,
                          z, NHEADS * Hh, 0);
    gat_scores_k<<<(Nn * NHEADS * 32 + 127) / 128, 128>>>(al, ar);
    gat_final_k<<<Nn, 256>>>(neighbors, graph_ids, Wr, br, out);
}

// round 6
// speedup vs baseline: 2.4573x; 1.1098x over previous
#include <cuda_runtime.h>
#include <stdint.h>
#include <math.h>

#define Nn 4096
#define Hh 500
#define Dd 8
#define NHEADS 5

#define BM 128
#define BN 128
#define BK 16
#define ASTRIDE 20    // 16 + 4 pad
#define BSTRIDE 132   // 128 + 4 pad
#define NKT 32        // ceil(500/16) k-tiles per part

// ---------------- scratch (static device globals; no allocation) ----------------
__device__ float g_xA[Nn * Hh];
__device__ float g_xB[Nn * Hh];
__device__ float g_h[Nn * Hh];
__device__ float g_c[Nn * Hh];
__device__ float g_gates[Nn * 4 * Hh];
__device__ float g_z[Nn * NHEADS * Hh];
__device__ float g_el[Nn * NHEADS];
__device__ float g_er[Nn * NHEADS];

// ---------------- utility kernels ----------------
__global__ void zero_k(float* p, int n) {
    int i = blockIdx.x * blockDim.x + threadIdx.x;
    if (i < n) p[i] = 0.f;
}

__global__ void embed_k(const int* __restrict__ ids, const float* __restrict__ emb,
                        float* __restrict__ x) {
    int i = blockIdx.x * blockDim.x + threadIdx.x;
    if (i < Nn * Hh) {
        int n = i / Hh, c = i % Hh;
        x[i] = emb[ids[n] * Hh + c];
    }
}

// round-to-nearest tf32 (unbiased)
__device__ __forceinline__ float tf32r(float x) {
    unsigned int u;
    asm("cvt.rna.tf32.f32 %0, %1;" : "=r"(u) : "f"(x));
    return __uint_as_float(u);
}

__device__ __forceinline__ void mma_tf32(float c[4], float a0, float a1, float a2, float a3,
                                         float b0, float b1) {
    asm volatile(
        "mma.sync.aligned.m16n8k8.row.col.f32.tf32.tf32.f32 "
        "{%0,%1,%2,%3}, {%4,%5,%6,%7}, {%8,%9}, {%0,%1,%2,%3};"
        : "+f"(c[0]), "+f"(c[1]), "+f"(c[2]), "+f"(c[3])
        : "r"(__float_as_uint(a0)), "r"(__float_as_uint(a1)),
          "r"(__float_as_uint(a2)), "r"(__float_as_uint(a3)),
          "r"(__float_as_uint(b0)), "r"(__float_as_uint(b1)));
}

// ---------------- tensor-core tf32 GEMM: 128x128 block, 4 warps of 64x64 ----------------
// C[M, Ncols] = act( A @ B + bias0 + bias1 )
// A (virtual, K = 500 or 1000):
//   part0 rows: X0[ nbr? nbr[m*Dd+t] : m ][k]   k in [0,500)
//   part1 rows: X1[ m ][k-500]                   (skipped if X1 == nullptr)
__global__ __launch_bounds__(128, 2) void gemm_mma(
    const float* __restrict__ X0, const int* __restrict__ nbr, int t,
    const float* __restrict__ X1,
    const float* __restrict__ B0, const float* __restrict__ B1,
    const float* __restrict__ bias0, const float* __restrict__ bias1,
    float* __restrict__ C, int Ncols, int act)
{
    __shared__ float As[2][BM * ASTRIDE];
    __shared__ float Bs[2][BK * BSTRIDE];

    const int tid = threadIdx.x;
    const int bm = blockIdx.y * BM;
    const int bn = blockIdx.x * BN;
    const int lane = tid & 31;
    const int warp = tid >> 5;
    const int g = lane >> 2, tig = lane & 3;
    const int am0 = (warp >> 1) * 64;      // warp M origin (0 or 64)
    const int bn0 = (warp & 1) * 64;       // warp N origin (0 or 64)

    // loader roles: A -> thread = one row, 16 k's; B -> 16 rows x 8 col-chunks
    const int brw = tid >> 3;              // B row 0..15
    const int bc0 = (tid & 7) * 16;        // B col 0..112

    const int arow0 = nbr ? nbr[(bm + tid) * Dd + t] : (bm + tid);
    const float* Arow0 = X0 + (size_t)arow0 * Hh;
    const float* Arow1 = X1 ? (X1 + (size_t)(bm + tid) * Hh) : nullptr;

    const int ntiles = (X1 ? 2 : 1) * NKT;

    float acc[4][8][4];
#pragma unroll
    for (int mt = 0; mt < 4; mt++)
#pragma unroll
        for (int nt = 0; nt < 8; nt++)
#pragma unroll
            for (int r = 0; r < 4; r++) acc[mt][nt][r] = 0.f;

    float a_reg[16], b_reg[16];

    // tile loader: global -> registers
    auto load_tile = [&](int tt) {
        const int part = (tt >= NKT) ? 1 : 0;
        const int k0 = (tt - part * NKT) * BK;
        const float* Arow = part ? Arow1 : Arow0;
        const float* Bw = part ? B1 : B0;
#pragma unroll
        for (int q = 0; q < 4; q++) {
            const int k = k0 + q * 4;
            if (k + 4 <= Hh) {
                float4 v = *reinterpret_cast<const float4*>(Arow + k);
                a_reg[q*4+0]=v.x; a_reg[q*4+1]=v.y; a_reg[q*4+2]=v.z; a_reg[q*4+3]=v.w;
            } else {
#pragma unroll
                for (int i = 0; i < 4; i++)
                    a_reg[q*4+i] = (k + i < Hh) ? Arow[k + i] : 0.f;
            }
        }
        const int brow = k0 + brw;
        const bool rok = brow < Hh;
        const float* Bp = Bw + (size_t)brow * Ncols;
#pragma unroll
        for (int q = 0; q < 4; q++) {
            const int cb = bn + bc0 + q * 4;
            if (rok && cb + 4 <= Ncols) {
                float4 v = *reinterpret_cast<const float4*>(Bp + cb);
                b_reg[q*4+0]=v.x; b_reg[q*4+1]=v.y; b_reg[q*4+2]=v.z; b_reg[q*4+3]=v.w;
            } else {
#pragma unroll
                for (int i = 0; i < 4; i++)
                    b_reg[q*4+i] = (rok && cb + i < Ncols) ? Bp[cb + i] : 0.f;
            }
        }
    };

    auto store_tile = [&](int buf) {
        float* ap = &As[buf][tid * ASTRIDE];
#pragma unroll
        for (int i = 0; i < 16; i++) ap[i] = tf32r(a_reg[i]);
        float* bp = &Bs[buf][brw * BSTRIDE + bc0];
#pragma unroll
        for (int i = 0; i < 16; i++) bp[i] = tf32r(b_reg[i]);
    };

    // prologue: tile 0 -> buffer 0
    load_tile(0);
    store_tile(0);
    __syncthreads();

    for (int tt = 0; tt < ntiles; tt++) {
        const int buf = tt & 1;
        const bool more = (tt + 1 < ntiles);
        if (more) load_tile(tt + 1);          // long-latency global loads first

        const float* Asb = As[buf];
        const float* Bsb = Bs[buf];
#pragma unroll
        for (int kk = 0; kk < 2; kk++) {
            const int k8 = kk * 8;
            float fa0[4], fa1[4], fa2[4], fa3[4];
#pragma unroll
            for (int mt = 0; mt < 4; mt++) {
                const int r = am0 + mt * 16 + g;
                fa0[mt] = Asb[r * ASTRIDE + k8 + tig];
                fa1[mt] = Asb[(r + 8) * ASTRIDE + k8 + tig];
                fa2[mt] = Asb[r * ASTRIDE + k8 + tig + 4];
                fa3[mt] = Asb[(r + 8) * ASTRIDE + k8 + tig + 4];
            }
            float fb0[8], fb1[8];
#pragma unroll
            for (int nt = 0; nt < 8; nt++) {
                const int cn = bn0 + nt * 8 + g;
                fb0[nt] = Bsb[(k8 + tig) * BSTRIDE + cn];
                fb1[nt] = Bsb[(k8 + tig + 4) * BSTRIDE + cn];
            }
#pragma unroll
            for (int mt = 0; mt < 4; mt++)
#pragma unroll
                for (int nt = 0; nt < 8; nt++)
                    mma_tf32(acc[mt][nt], fa0[mt], fa1[mt], fa2[mt], fa3[mt],
                             fb0[nt], fb1[nt]);
        }

        if (more) store_tile(buf ^ 1);        // write NEXT buffer (safe: other warps read buf)
        __syncthreads();
    }

    // ---- epilogue: bias + optional relu, float2 stores ----
#pragma unroll
    for (int mt = 0; mt < 4; mt++) {
        const int row0 = bm + am0 + mt * 16 + g;
#pragma unroll
        for (int nt = 0; nt < 8; nt++) {
            const int col = bn + bn0 + nt * 8 + 2 * tig;
            if (col < Ncols) {
                float bia = 0.f, bib = 0.f;
                if (bias0) { bia = bias0[col]; bib = bias0[col + 1]; }
                if (bias1) { bia += bias1[col]; bib += bias1[col + 1]; }
                float v0 = acc[mt][nt][0] + bia;
                float v1 = acc[mt][nt][1] + bib;
                float v2 = acc[mt][nt][2] + bia;
                float v3 = acc[mt][nt][3] + bib;
                if (act) {
                    v0 = fmaxf(v0, 0.f); v1 = fmaxf(v1, 0.f);
                    v2 = fmaxf(v2, 0.f); v3 = fmaxf(v3, 0.f);
                }
                *reinterpret_cast<float2*>(&C[(size_t)row0 * Ncols + col]) =
                    make_float2(v0, v1);
                *reinterpret_cast<float2*>(&C[(size_t)(row0 + 8) * Ncols + col]) =
                    make_float2(v2, v3);
            }
        }
    }
}

// ---------------- LSTM cell update (torch gate order i,f,g,o) ----------------
__global__ void lstm_cell_k(int first) {
    int i = blockIdx.x * blockDim.x + threadIdx.x;
    if (i >= Nn * Hh) return;
    int n = i / Hh, j = i % Hh;
    const float* g = g_gates + (size_t)n * (4 * Hh);
    float gi = g[j];
    float gf = g[j + Hh];
    float gg = g[j + 2 * Hh];
    float go = g[j + 3 * Hh];
    float si = 1.f / (1.f + expf(-gi));
    float sf = 1.f / (1.f + expf(-gf));
    float so = 1.f / (1.f + expf(-go));
    float cprev = first ? 0.f : g_c[i];
    float c = sf * cprev + si * tanhf(gg);
    g_c[i] = c;
    g_h[i] = so * tanhf(c);
}

// ---------------- GAT attention scores: el/er per (node, head) ----------------
__global__ void gat_scores_k(const float* __restrict__ al, const float* __restrict__ ar) {
    int w = (blockIdx.x * blockDim.x + threadIdx.x) >> 5;
    int lane = threadIdx.x & 31;
    if (w >= Nn * NHEADS) return;
    int n = w / NHEADS, hd = w % NHEADS;
    const float* zr = g_z + (size_t)n * (NHEADS * Hh) + hd * Hh;
    float sl = 0.f, sr = 0.f;
    for (int c = lane; c < Hh; c += 32) {
        float zv = zr[c];
        sl = fmaf(zv, al[hd * Hh + c], sl);
        sr = fmaf(zv, ar[hd * Hh + c], sr);
    }
#pragma unroll
    for (int o = 16; o; o >>= 1) {
        sl += __shfl_xor_sync(0xFFFFFFFFu, sl, o);
        sr += __shfl_xor_sync(0xFFFFFFFFu, sr, o);
    }
    if (lane == 0) { g_el[w] = sl; g_er[w] = sr; }
}

// ---------------- fused GAT aggregate + relu + head-mean + elu + readout + segsum ----------------
__global__ __launch_bounds__(256) void gat_final_k(
    const int* __restrict__ nbr, const int* __restrict__ gid,
    const float* __restrict__ Wr, const float* __restrict__ br,
    float* __restrict__ out)
{
    int n = blockIdx.x;
    int tid = threadIdx.x;
    __shared__ float alpha[NHEADS][Dd];
    __shared__ int nb[Dd];
    __shared__ float red[256];

    if (tid < Dd) nb[tid] = nbr[n * Dd + tid];
    __syncthreads();

    if (tid < NHEADS * Dd) {
        int hd = tid / Dd, d = tid % Dd;
        float e = g_el[nb[d] * NHEADS + hd] + g_er[n * NHEADS + hd];
        alpha[hd][d] = (e > 0.f) ? e : 0.2f * e;   // leaky_relu slope 0.2
    }
    __syncthreads();
    if (tid < NHEADS) {
        float mx = -1e30f;
#pragma unroll
        for (int d = 0; d < Dd; d++) mx = fmaxf(mx, alpha[tid][d]);
        float ex[Dd]; float s = 0.f;
#pragma unroll
        for (int d = 0; d < Dd; d++) { ex[d] = expf(alpha[tid][d] - mx); s += ex[d]; }
        float inv = 1.f / s;
#pragma unroll
        for (int d = 0; d < Dd; d++) alpha[tid][d] = ex[d] * inv;
    }
    __syncthreads();

    float accum = 0.f;
    for (int c = tid; c < Hh; c += 256) {
        float mean = 0.f;
#pragma unroll
        for (int hd = 0; hd < NHEADS; hd++) {
            float s = 0.f;
#pragma unroll
            for (int d = 0; d < Dd; d++)
                s = fmaf(alpha[hd][d],
                         g_z[(size_t)nb[d] * (NHEADS * Hh) + hd * Hh + c], s);
            mean += fmaxf(s, 0.f);    // relu BEFORE head-mean
        }
        mean *= (1.f / NHEADS);
        float e = (mean > 0.f) ? mean : (expf(mean) - 1.f);   // elu
        accum = fmaf(e, Wr[c], accum);
    }
    red[tid] = accum;
    __syncthreads();
    for (int s = 128; s > 0; s >>= 1) {
        if (tid < s) red[tid] += red[tid + s];
        __syncthreads();
    }
    if (tid == 0) atomicAdd(&out[gid[n]], red[0] + br[0]);
}

// ---------------- launch ----------------
extern "C" void kernel_launch(void* const* d_in, const int* in_sizes, int n_in,
                              void* d_out, int out_size) {
    const int* node_ids  = (const int*)d_in[0];
    const int* neighbors = (const int*)d_in[1];
    const int* graph_ids = (const int*)d_in[2];
    // d_in[3] = num_graphs (unused; out_size gives G)
    const float* emb = (const float*)d_in[4];
    const float* W[3][7];   // Wih, Whh, bih, bhh, Wself, Wneigh, b
    int p = 5;
    for (int l = 0; l < 3; l++)
        for (int q = 0; q < 7; q++) W[l][q] = (const float*)d_in[p++];
    const float* Wg = (const float*)d_in[p++];
    const float* al = (const float*)d_in[p++];
    const float* ar = (const float*)d_in[p++];
    const float* Wr = (const float*)d_in[p++];
    const float* br = (const float*)d_in[p++];
    float* out = (float*)d_out;

    float *xA, *xB, *h, *gates, *z;
    cudaGetSymbolAddress((void**)&xA, g_xA);
    cudaGetSymbolAddress((void**)&xB, g_xB);
    cudaGetSymbolAddress((void**)&h, g_h);
    cudaGetSymbolAddress((void**)&gates, g_gates);
    cudaGetSymbolAddress((void**)&z, g_z);

    const int NH = Nn * Hh;
    zero_k<<<1, 64>>>(out, out_size);
    embed_k<<<(NH + 255) / 256, 256>>>(node_ids, emb, xA);

    dim3 gGates((4 * Hh + BN - 1) / BN, Nn / BM);      // 16 x 32
    dim3 gFc((Hh + BN - 1) / BN, Nn / BM);             // 4 x 32
    dim3 gZ((NHEADS * Hh + BN - 1) / BN, Nn / BM);     // 20 x 32

    float* xin = xA;
    float* xout = xB;
    for (int l = 0; l < 3; l++) {
        for (int t = 0; t < Dd; t++) {
            // t == 0: h == 0 -> skip the h@Whh half entirely.
            gemm_mma<<<gGates, 128>>>(xin, neighbors, t,
                                      (t == 0) ? nullptr : h,
                                      W[l][0], W[l][1], W[l][2], W[l][3],
                                      gates, 4 * Hh, 0);
            lstm_cell_k<<<(NH + 255) / 256, 256>>>(t == 0 ? 1 : 0);
        }
        gemm_mma<<<gFc, 128>>>(xin, nullptr, 0, h,
                               W[l][4], W[l][5], W[l][6], nullptr,
                               xout, Hh, 1);
        float* tmp = xin; xin = xout; xout = tmp;
    }

    gemm_mma<<<gZ, 128>>>(xin, nullptr, 0, nullptr,
                          Wg, nullptr, nullptr, nullptr,
                          z, NHEADS * Hh, 0);
    gat_scores_k<<<(Nn * NHEADS * 32 + 127) / 128, 128>>>(al, ar);
    gat_final_k<<<Nn, 256>>>(neighbors, graph_ids, Wr, br, out);
}